// round 2
// baseline (speedup 1.0000x reference)
#include <cuda_runtime.h>
#include <cuda_bf16.h>
#include <math.h>

// PCEN: m = EMA(x, S=0.5); out = (x / (eps+m)^alpha + delta)^r - delta^r
// x: [1024, 32768] fp32 row-major; alpha, r, delta: fp32 scalars (device, size 1).
//
// Strategy:
//  - Row split into 4 segments of SEG=8192; each block owns one segment.
//  - Two-pass chunked scan: 256 threads x 32-elem chunks. Pass 1 computes the
//    zero-start local EMA b_k of each chunk. Exact-to-5e-20 carry:
//    carry_k = b_{k-1} + 2^-32 * b_{k-2}  (0.5^32 decay of a 32-elem chunk).
//  - 64-element halo (2 extra chunks) before each segment makes blocks
//    independent (error 0.5^64, vastly below the 1e-3 tolerance).
//  - Shared staging with XOR-at-float4 swizzle: slot j of chunk c stored at
//    j ^ (c & 7). Conflict-free for both coalesced staging and per-chunk reads.
//  - Pointwise: ex2(-alpha*lg2(eps+m)) avoids the division; r==0.5 (uniform
//    runtime check) uses sqrt.approx -> 3 MUFU/element.

#define FRAMES   32768
#define SEG      8192
#define NTHREADS 256
#define CHUNK    32
#define HALO     64
#define NCHUNK   (SEG / CHUNK)          // 256
#define SEGS_PER_ROW (FRAMES / SEG)     // 4
#define F4_ITERS (SEG / 4 / NTHREADS)   // 8

__device__ __forceinline__ float fast_lg2(float v) {
    float r_;
    asm("lg2.approx.f32 %0, %1;" : "=f"(r_) : "f"(v));
    return r_;
}
__device__ __forceinline__ float fast_ex2(float v) {
    float r_;
    asm("ex2.approx.f32 %0, %1;" : "=f"(r_) : "f"(v));
    return r_;
}
__device__ __forceinline__ float fast_sqrt(float v) {
    float r_;
    asm("sqrt.approx.f32 %0, %1;" : "=f"(r_) : "f"(v));
    return r_;
}

__device__ __forceinline__ float pcen_elem(float xv, float& m, float na,
                                           float r, float delta, float dr,
                                           bool rhalf) {
    m = 0.5f * (m + xv);                       // EMA step
    float l = fast_lg2(m + 1e-6f);             // MUFU.LG2
    float p = fast_ex2(na * l);                // MUFU.EX2  -> (eps+m)^(-alpha)
    float u = fmaf(xv, p, delta);              // u >= delta = 2 > 0
    float s;
    if (rhalf) {
        s = fast_sqrt(u);                      // MUFU.SQRT
    } else {
        s = fast_ex2(r * fast_lg2(u));
    }
    return s - dr;
}

__global__ void __launch_bounds__(NTHREADS) pcen_kernel(
    const float* __restrict__ x,
    const float* __restrict__ p_alpha,
    const float* __restrict__ p_r,
    const float* __restrict__ p_delta,
    float* __restrict__ out)
{
    __shared__ float data[SEG];          // swizzled segment (32 KB)
    __shared__ float halo[HALO];         // 64 preceding elements (unswizzled)
    __shared__ float sb[NCHUNK + 2];     // sb[0..1]=halo chunk EMAs, sb[k+2]=b_k

    const int t = threadIdx.x;
    const size_t g0 = (size_t)blockIdx.x * SEG;
    const bool first_seg = ((blockIdx.x & (SEGS_PER_ROW - 1)) == 0);

    // ---- stage in: coalesced global -> swizzled shared ----
    const float4* gin = (const float4*)(x + g0);
    #pragma unroll
    for (int i = 0; i < F4_ITERS; ++i) {
        int g = i * NTHREADS + t;                   // float4 index in segment
        float4 v = gin[g];
        int c = g >> 3;                             // chunk
        int j = g & 7;                              // slot within chunk
        *(float4*)&data[(c << 5) + ((j ^ (c & 7)) << 2)] = v;
    }
    if (t < HALO / 4) {
        float4 v;
        if (first_seg) v = make_float4(0.f, 0.f, 0.f, 0.f);
        else           v = *(const float4*)(x + g0 - HALO + 4 * t);
        *(float4*)&halo[4 * t] = v;
    }
    __syncthreads();

    // ---- pass 1: zero-start local EMA per chunk ----
    {
        float m = 0.f;
        #pragma unroll
        for (int j = 0; j < CHUNK / 4; ++j) {
            float4 v = *(const float4*)&data[(t << 5) + ((j ^ (t & 7)) << 2)];
            m = 0.5f * (m + v.x);
            m = 0.5f * (m + v.y);
            m = 0.5f * (m + v.z);
            m = 0.5f * (m + v.w);
        }
        sb[t + 2] = m;
    }
    if (t < 2) {                                    // halo chunks -2, -1
        float hm = 0.f;
        #pragma unroll
        for (int j = 0; j < CHUNK; ++j)
            hm = 0.5f * (hm + halo[t * CHUNK + j]);
        sb[t] = hm;
    }
    __syncthreads();

    // ---- carry: M_k = b_{k-1} + 2^-32 * b_{k-2}  (abs err <= 0.5^64) ----
    const float q = 0x1p-32f;
    float carry = fmaf(q, sb[t], sb[t + 1]);

    const float alpha = *p_alpha;
    const float r     = *p_r;
    const float delta = *p_delta;
    const float dr    = fast_ex2(r * fast_lg2(delta));
    const float na    = -alpha;
    const bool rhalf  = (r == 0.5f);

    // ---- pass 2: EMA with carry + PCEN pointwise, write back in place ----
    {
        float m = carry;
        #pragma unroll
        for (int j = 0; j < CHUNK / 4; ++j) {
            float* slot = &data[(t << 5) + ((j ^ (t & 7)) << 2)];
            float4 v = *(const float4*)slot;
            float4 o;
            o.x = pcen_elem(v.x, m, na, r, delta, dr, rhalf);
            o.y = pcen_elem(v.y, m, na, r, delta, dr, rhalf);
            o.z = pcen_elem(v.z, m, na, r, delta, dr, rhalf);
            o.w = pcen_elem(v.w, m, na, r, delta, dr, rhalf);
            *(float4*)slot = o;
        }
    }
    __syncthreads();

    // ---- stage out: swizzled shared -> coalesced global ----
    float4* gout = (float4*)(out + g0);
    #pragma unroll
    for (int i = 0; i < F4_ITERS; ++i) {
        int g = i * NTHREADS + t;
        int c = g >> 3;
        int j = g & 7;
        gout[g] = *(const float4*)&data[(c << 5) + ((j ^ (c & 7)) << 2)];
    }
}

extern "C" void kernel_launch(void* const* d_in, const int* in_sizes, int n_in,
                              void* d_out, int out_size) {
    (void)n_in; (void)out_size;
    const float* x     = (const float*)d_in[0];
    const float* alpha = (const float*)d_in[1];
    const float* r     = (const float*)d_in[2];
    const float* delta = (const float*)d_in[3];
    float* out = (float*)d_out;

    int total  = in_sizes[0];            // 1024 * 32768 = 33554432
    int blocks = total / SEG;            // 4096

    pcen_kernel<<<blocks, NTHREADS>>>(x, alpha, r, delta, out);
}